// round 9
// baseline (speedup 1.0000x reference)
#include <cuda_runtime.h>
#include <math.h>
#include <stdint.h>

// ---------------------------------------------------------------------------
// HierarchicalVAE fused: cluster-4 multicast weight streaming, warp-specialized
// producer, MLP on 512 threads, rasterizer on 784 threads (1 px/thread).
// grid = 128 CTAs (1 per batch), 32 clusters x 4 CTAs, 832 threads:
//   warps 0-15 (tid 0-511):   MLP chain (tile consumers) + raster
//   warps 16-24 (tid 512-799): park at raster gate, then raster
//   warp 25 (tid 800):         producer - 44 tiles, 3-stage x 64KB ring
// Named barrier 1 (512 thr) = MLP sync; barrier 2 (800 thr) = raster gate.
// ---------------------------------------------------------------------------

#define BATCH 128
#define TPB 832
#define NC 512                      // MLP consumer threads
#define NGATE 800                   // warps 0-24 at raster gate
#define CLUSTER 4
#define NSTAGES 3
#define STAGE_FLOATS 16384          // 64KB
#define STAGE_BYTES  65536
#define NT 44
#define HALFC 14.0f
#define SCALEC 12.0f

#define OUT_R  0
#define OUT_MU (BATCH*784)
#define OUT_LV (OUT_MU + BATCH*64)
#define OUT_CP (OUT_LV + BATCH*64)
#define OUT_W  (OUT_CP + BATCH*64)
#define OUT_A  (OUT_W + BATCH*2)

struct WPtrs {
    const float *ew1, *ew2, *muw, *lvw, *dw1, *dw2, *cpw, *wdw, *alw, *rw1, *rw2;
};

__device__ __forceinline__ uint32_t smem_u32(const void* p) {
    return (uint32_t)__cvta_generic_to_shared(p);
}
__device__ __forceinline__ void mbar_init(uint32_t addr, uint32_t count) {
    asm volatile("mbarrier.init.shared.b64 [%0], %1;" :: "r"(addr), "r"(count) : "memory");
}
__device__ __forceinline__ void mbar_wait(uint32_t addr, uint32_t parity) {
    asm volatile(
        "{\n\t.reg .pred P;\n"
        "W_%=:\n\t"
        "mbarrier.try_wait.parity.acquire.cta.shared::cta.b64 P, [%0], %1, 0x989680;\n\t"
        "@P bra.uni D_%=;\n\t"
        "bra.uni W_%=;\n"
        "D_%=:\n\t}"
        :: "r"(addr), "r"(parity) : "memory");
}
__device__ __forceinline__ void mbar_expect_tx(uint32_t addr, uint32_t bytes) {
    asm volatile("mbarrier.arrive.expect_tx.shared.b64 _, [%0], %1;"
                 :: "r"(addr), "r"(bytes) : "memory");
}
__device__ __forceinline__ void mbar_arrive_rank(uint32_t addr, uint32_t rank) {
    asm volatile(
        "{\n\t.reg .b32 ra;\n\t"
        "mapa.shared::cluster.u32 ra, %0, %1;\n\t"
        "mbarrier.arrive.shared::cluster.b64 _, [ra];\n\t}"
        :: "r"(addr), "r"(rank) : "memory");
}
__device__ __forceinline__ void cluster_sync_all() {
    asm volatile("barrier.cluster.arrive.aligned;" ::: "memory");
    asm volatile("barrier.cluster.wait.aligned;" ::: "memory");
}
__device__ __forceinline__ void bulk_mc(uint32_t dst, const void* src, uint32_t bytes,
                                        uint32_t mbar, uint16_t mask) {
    asm volatile(
        "cp.async.bulk.shared::cluster.global.mbarrier::complete_tx::bytes.multicast::cluster "
        "[%0], [%1], %2, [%3], %4;"
        :: "r"(dst), "l"(src), "r"(bytes), "r"(mbar), "h"(mask) : "memory");
}

__device__ __forceinline__ float seluf(float x) {
    const float sc = 1.0507009873554805f;
    const float al = 1.6732632423543772f;
    return x > 0.0f ? sc * x : sc * al * (expf(x) - 1.0f);
}
__device__ __forceinline__ float lrelu(float x) { return x >= 0.0f ? x : 0.2f * x; }
__device__ __forceinline__ float sigm(float x)  { return 1.0f / (1.0f + expf(-x)); }

// Tile table (44 tiles, 64KB stages) — identical to R6/R7.
__device__ __forceinline__ int tile_segs(int n, const WPtrs& p,
                                         const char* srcs[2], uint32_t szs[2]) {
    if (n < 13) { int r0 = n * 64; int rows = (r0 + 64 <= 784) ? 64 : (784 - r0);
                  srcs[0] = (const char*)(p.ew1 + r0 * 256); szs[0] = rows * 1024; return 1; }
    n -= 13;
    if (n < 4)  { srcs[0] = (const char*)(p.ew2 + n * 64 * 256); szs[0] = 65536; return 1; }
    n -= 4;
    if (n == 0) { srcs[0] = (const char*)p.muw; szs[0] = 65536; return 1; } n--;
    if (n == 0) { srcs[0] = (const char*)p.lvw; szs[0] = 65536; return 1; } n--;
    if (n < 2)  { srcs[0] = (const char*)(p.dw1 + n * 32 * 512); szs[0] = 65536; return 1; }
    n -= 2;
    if (n < 16) { srcs[0] = (const char*)(p.dw2 + n * 32 * 512); szs[0] = 65536; return 1; }
    n -= 16;
    if (n == 0) { srcs[0] = (const char*)p.cpw; szs[0] = 57344; return 1; } n--;
    if (n == 0) { srcs[0] = (const char*)p.wdw; szs[0] = 4096;
                  srcs[1] = (const char*)p.alw; szs[1] = 4096; return 2; } n--;
    if (n < 3)  { int r0 = n * 32; int rows = (r0 + 32 <= 92) ? 32 : (92 - r0);
                  srcs[0] = (const char*)(p.rw1 + r0 * 512); szs[0] = rows * 2048; return 1; }
    n -= 3;
    srcs[0] = (const char*)(p.rw2 + n * 256 * 52); szs[0] = 53248; return 1;
}

__device__ __forceinline__ void produce(int j, uint32_t bar_base, uint32_t ring_base,
                                        const WPtrs& p, uint32_t rank) {
    const int s = j % NSTAGES;
    mbar_wait(bar_base + s * 16 + 8, 1u ^ ((uint32_t)(j / NSTAGES) & 1u));
    const char* srcs[2]; uint32_t szs[2];
    int ns = tile_segs(j, p, srcs, szs);
    uint32_t total = szs[0] + ((ns > 1) ? szs[1] : 0u);
    const uint32_t full = bar_base + s * 16;
    mbar_expect_tx(full, total);
    uint32_t dst = ring_base + s * STAGE_BYTES;
    for (int k = 0; k < ns; k++) {
        uint32_t slice = szs[k] >> 2;   // /CLUSTER
        bulk_mc(dst + rank * slice, srcs[k] + rank * slice, slice, full, 0xF);
        dst += szs[k];
    }
}

#define CONS_SYNC() asm volatile("bar.sync 1, %0;" :: "n"(NC) : "memory")
#define GATE_SYNC() asm volatile("bar.sync 2, %0;" :: "n"(NGATE) : "memory")

#define TILE_BEGIN() do { \
        mbar_wait(bar_base + (tn % NSTAGES) * 16, (uint32_t)(tn / NSTAGES) & 1u); \
        ws = wb + (tn % NSTAGES) * STAGE_FLOATS; } while (0)

#define TILE_END() do { __syncwarp(); \
        if ((tid & 31) == 0) { uint32_t e = bar_base + (tn % NSTAGES) * 16 + 8; \
            mbar_arrive_rank(e, 0); mbar_arrive_rank(e, 1); \
            mbar_arrive_rank(e, 2); mbar_arrive_rank(e, 3); } \
        tn++; } while (0)

__global__ void __launch_bounds__(TPB, 1) __cluster_dims__(CLUSTER, 1, 1)
fused_kernel(
    const float* __restrict__ x,    const float* __restrict__ eps,
    const float* __restrict__ ew1,  const float* __restrict__ eb1,
    const float* __restrict__ ew2,  const float* __restrict__ eb2,
    const float* __restrict__ muw,  const float* __restrict__ mub,
    const float* __restrict__ lvw,  const float* __restrict__ lvb,
    const float* __restrict__ dw1,  const float* __restrict__ db1,
    const float* __restrict__ dw2,  const float* __restrict__ db2,
    const float* __restrict__ cpw,  const float* __restrict__ cpb,
    const float* __restrict__ rw1,  const float* __restrict__ rb1,
    const float* __restrict__ rw2w, const float* __restrict__ rb2,
    const float* __restrict__ wdw,  const float* __restrict__ wdb,
    const float* __restrict__ alw,  const float* __restrict__ alb,
    float* __restrict__ out)
{
    extern __shared__ float wb[];   // NSTAGES * STAGE_FLOATS

    const int b   = blockIdx.x;
    const int tid = threadIdx.x;

    __shared__ alignas(16) unsigned long long mbars[NSTAGES * 2];
    __shared__ float sx[784];
    __shared__ float h1[256];
    __shared__ float h2[256];
    __shared__ float muv[64];
    __shared__ float hin[92];
    __shared__ float d1[512];
    __shared__ float d2[512];
    __shared__ float r1[512];
    __shared__ float pts[52];
    __shared__ float red[NC];
    __shared__ float red2[NC];
    __shared__ float qx[64], qy[64], wa[4];
    __shared__ alignas(16) float4 pt4[64];   // (x, y, |q|^2, 1/dy)

    WPtrs wp; wp.ew1 = ew1; wp.ew2 = ew2; wp.muw = muw; wp.lvw = lvw;
    wp.dw1 = dw1; wp.dw2 = dw2; wp.cpw = cpw; wp.wdw = wdw; wp.alw = alw;
    wp.rw1 = rw1; wp.rw2 = rw2w;

    const uint32_t bar_base  = smem_u32(mbars);
    const uint32_t ring_base = smem_u32(wb);
    uint32_t rank;
    asm("mov.u32 %0, %%cluster_ctarank;" : "=r"(rank));

    if (tid == 0) {
        #pragma unroll
        for (int s = 0; s < NSTAGES; s++) {
            mbar_init(bar_base + s * 16, 1);         // full: 1 expect_tx arrive
            mbar_init(bar_base + s * 16 + 8, 64);    // empty: 16 MLP warps x 4 CTAs
        }
    }
    __syncthreads();
    cluster_sync_all();

    if (tid >= NGATE) {
        // ---------------- producer warp (warp 25) ----------------
        if (tid == NGATE) {
            for (int j = 0; j < NT; j++) produce(j, bar_base, ring_base, wp, rank);
        }
    } else {
        if (tid < NC) {
            // ---------------- MLP (512 threads, 16 warps) ----------------
            for (int i = tid; i < 784; i += NC) sx[i] = x[b * 784 + i];
            CONS_SYNC();

            int tn = 0;
            float* ws;

            // enc1: 784 -> 256 (13 tiles), 2-way K split
            {
                const int g = tid >> 8, o = tid & 255;
                float acc = (g == 0) ? eb1[o] : 0.0f;
                for (int t = 0; t < 13; t++) {
                    TILE_BEGIN();
                    const int rows = (t < 12) ? 64 : 16, half = rows >> 1;
                    const int r0 = g * half, gr = t * 64 + r0;
                    #pragma unroll 8
                    for (int r = 0; r < half; r++)
                        acc = fmaf(sx[gr + r], ws[(r0 + r) * 256 + o], acc);
                    TILE_END();
                }
                red[tid] = acc;
            }
            CONS_SYNC();
            if (tid < 256) h1[tid] = lrelu(red[tid] + red[256 + tid]);
            CONS_SYNC();

            // enc2: 256 -> 256 (4 tiles), 2-way K split
            {
                const int g = tid >> 8, o = tid & 255;
                float acc = (g == 0) ? eb2[o] : 0.0f;
                for (int t = 0; t < 4; t++) {
                    TILE_BEGIN();
                    const int r0 = g * 32, gr = t * 64 + r0;
                    #pragma unroll 8
                    for (int r = 0; r < 32; r++)
                        acc = fmaf(h1[gr + r], ws[(r0 + r) * 256 + o], acc);
                    TILE_END();
                }
                red[tid] = acc;
            }
            CONS_SYNC();
            if (tid < 256) h2[tid] = lrelu(red[tid] + red[256 + tid]);
            CONS_SYNC();

            // mu: 256 -> 64 (1 tile), 8-way K split
            {
                const int g = tid >> 6, l = tid & 63;
                TILE_BEGIN();
                float a = 0.0f;
                #pragma unroll 8
                for (int i = 0; i < 32; i++) {
                    int kl = g * 32 + i;
                    a = fmaf(h2[kl], ws[kl * 64 + l], a);
                }
                red[tid] = a;
                TILE_END();
            }
            CONS_SYNC();
            if (tid < 64) {
                float s = mub[tid];
                #pragma unroll
                for (int k = 0; k < 8; k++) s += red[k * 64 + tid];
                muv[tid] = s;
            }
            CONS_SYNC();

            // logvar: 256 -> 64 (1 tile), 8-way K split
            {
                const int g = tid >> 6, l = tid & 63;
                TILE_BEGIN();
                float a = 0.0f;
                #pragma unroll 8
                for (int i = 0; i < 32; i++) {
                    int kl = g * 32 + i;
                    a = fmaf(h2[kl], ws[kl * 64 + l], a);
                }
                red[tid] = a;
                TILE_END();
            }
            CONS_SYNC();
            if (tid < 64) {
                float lvV = lvb[tid];
                #pragma unroll
                for (int k = 0; k < 8; k++) lvV += red[k * 64 + tid];
                float m = muv[tid];
                out[OUT_MU + b * 64 + tid] = m;
                out[OUT_LV + b * 64 + tid] = lvV;
                hin[tid] = m + eps[b * 64 + tid] * expf(0.5f * lvV);
            }
            CONS_SYNC();

            // dec1: 64 -> 512 (2 tiles of 32 rows)
            {
                float a = db1[tid];
                for (int t = 0; t < 2; t++) {
                    TILE_BEGIN();
                    const int r0 = t * 32;
                    #pragma unroll 8
                    for (int r = 0; r < 32; r++)
                        a = fmaf(hin[r0 + r], ws[r * 512 + tid], a);
                    TILE_END();
                }
                d1[tid] = seluf(a);
            }
            CONS_SYNC();

            // dec2: 512 -> 512 (16 tiles of 32 rows)
            {
                float a = db2[tid];
                for (int t = 0; t < 16; t++) {
                    TILE_BEGIN();
                    const int r0 = t * 32;
                    #pragma unroll 8
                    for (int r = 0; r < 32; r++)
                        a = fmaf(d1[r0 + r], ws[r * 512 + tid], a);
                    TILE_END();
                }
                d2[tid] = seluf(a);
            }
            CONS_SYNC();

            // coarse cp: 512 -> 28 (1 tile), 16-way K split
            {
                const int g = tid >> 5, l = tid & 31;
                TILE_BEGIN();
                float a = 0.0f;
                if (l < 28) {
                    #pragma unroll 8
                    for (int i = 0; i < 32; i++) {
                        int kl = g * 32 + i;
                        a = fmaf(d2[kl], ws[kl * 28 + l], a);
                    }
                }
                red[tid] = a;
                TILE_END();
            }
            CONS_SYNC();
            if (tid < 28) {
                float s = cpb[tid];
                #pragma unroll
                for (int k = 0; k < 16; k++) s += red[k * 32 + tid];
                hin[64 + tid] = tanhf(s);
            }
            CONS_SYNC();

            // widths + alphas: 512 -> 2 each (1 fused tile)
            {
                const int pp = tid >> 8, l = tid & 255;
                TILE_BEGIN();
                float aw = fmaf(d2[l], ws[l * 2 + pp], 0.0f);
                aw = fmaf(d2[l + 256], ws[(l + 256) * 2 + pp], aw);
                float aa = fmaf(d2[l], ws[1024 + l * 2 + pp], 0.0f);
                aa = fmaf(d2[l + 256], ws[1024 + (l + 256) * 2 + pp], aa);
                red[tid] = aw; red2[tid] = aa;
                TILE_END();
            }
            CONS_SYNC();
            if (tid < 2) {
                const float* rp = &red[tid * 256];
                float s0 = 0, s1 = 0, s2 = 0, s3 = 0;
                #pragma unroll
                for (int j = 0; j < 64; j++) { s0 += rp[j]; s1 += rp[64 + j]; s2 += rp[128 + j]; s3 += rp[192 + j]; }
                float wv = sigm(wdb[tid] + ((s0 + s1) + (s2 + s3))) * 2.0f + 1.0f;
                wa[tid] = wv;
                out[OUT_W + b * 2 + tid] = wv;
            } else if (tid >= 32 && tid < 34) {
                const int pA = tid - 32;
                const float* rp = &red2[pA * 256];
                float s0 = 0, s1 = 0, s2 = 0, s3 = 0;
                #pragma unroll
                for (int j = 0; j < 64; j++) { s0 += rp[j]; s1 += rp[64 + j]; s2 += rp[128 + j]; s3 += rp[192 + j]; }
                float av = sigm(alb[pA] + ((s0 + s1) + (s2 + s3)));
                wa[2 + pA] = av;
                out[OUT_A + b * 2 + pA] = av;
            }
            CONS_SYNC();

            // refine1: 92 -> 512 (3 tiles)
            {
                float a = rb1[tid];
                for (int t = 0; t < 3; t++) {
                    TILE_BEGIN();
                    const int r0 = t * 32, rows = (t < 2) ? 32 : 28;
                    #pragma unroll 8
                    for (int r = 0; r < rows; r++)
                        a = fmaf(hin[r0 + r], ws[r * 512 + tid], a);
                    TILE_END();
                }
                r1[tid] = seluf(a);
            }
            CONS_SYNC();

            // refine2: 512 -> 52 (2 tiles of 256 rows), 8-way K split
            {
                const int g = tid >> 6, l = tid & 63;
                float a = 0.0f;
                for (int t = 0; t < 2; t++) {
                    TILE_BEGIN();
                    if (l < 52) {
                        #pragma unroll 8
                        for (int i = 0; i < 32; i++) {
                            int kl = g * 32 + i;
                            a = fmaf(r1[t * 256 + kl], ws[kl * 52 + l], a);
                        }
                    }
                    TILE_END();
                }
                red[tid] = a;
            }
            CONS_SYNC();
            if (tid < 52) {
                float s = rb2[tid];
                #pragma unroll
                for (int k = 0; k < 8; k++) s += red[k * 64 + tid];
                pts[tid] = tanhf(s) * SCALEC + HALFC;
            }
            CONS_SYNC();

            // control points out + bezier sample eval
            if (tid < 64) {
                const int p = tid >> 5, rem = tid & 31;
                {
                    int s = rem >> 3, k = (rem >> 1) & 3, d = rem & 1;
                    out[OUT_CP + b * 64 + tid] = pts[p * 26 + (3 * s + k) * 2 + d];
                }
                const int ss = rem >> 3, ti = rem & 7;
                float t  = (float)ti / 7.0f;
                float mt = 1.0f - t;
                float b0 = mt * mt * mt;
                float b1 = 3.0f * mt * mt * t;
                float b2 = 3.0f * mt * t * t;
                float b3 = t * t * t;
                int base = p * 26 + (3 * ss) * 2;
                float X = b0 * pts[base + 0] + b1 * pts[base + 2] + b2 * pts[base + 4] + b3 * pts[base + 6];
                float Y = b0 * pts[base + 1] + b1 * pts[base + 3] + b2 * pts[base + 5] + b3 * pts[base + 7];
                qx[tid] = X; qy[tid] = Y;
            }
            CONS_SYNC();
            if (tid < 64) {
                const int p = tid >> 5, m = tid & 31;
                float X = qx[tid], Y = qy[tid];
                float y1 = qy[p * 32 + ((m + 1) & 31)];
                float si = __fdiv_rn(1.0f, (y1 - Y) + 1e-8f);
                pt4[tid] = make_float4(X, Y, X * X + Y * Y, si);
            }
        }

        // ---------------- raster gate: warps 0-24 join ----------------
        GATE_SYNC();

        // ---------------- rasterizer: 1 pixel per thread ----------------
        if (tid < 784) {
            const int px = tid;
            const int pi = px / 28, pj = px - pi * 28;
            float syv[4], sxv[4], nxv[4], nyv[4], ssn[4], val[4];
            #pragma unroll
            for (int s = 0; s < 4; s++) {
                syv[s] = (float)pi + (0.25f + 0.5f * (float)(s >> 1));
                sxv[s] = (float)pj + (0.25f + 0.5f * (float)(s & 1));
                nxv[s] = -2.0f * sxv[s];
                nyv[s] = -2.0f * syv[s];
                ssn[s] = sxv[s] * sxv[s] + syv[s] * syv[s];
                val[s] = 1.0f;
            }
            #pragma unroll
            for (int p = 0; p < 2; p++) {
                const int base = p * 32;
                float mind2[4]; int nc[4]; bool c0[4];
                float4 e = pt4[base];
                #pragma unroll
                for (int s = 0; s < 4; s++) {
                    mind2[s] = 3.402823e38f; nc[s] = 0; c0[s] = e.y > syv[s];
                }
                #pragma unroll 8
                for (int m = 0; m < 32; m++) {
                    const float4 e1 = pt4[base + ((m + 1) & 31)];
                    const float dx = e1.x - e.x;
                    #pragma unroll
                    for (int s = 0; s < 4; s++) {
                        // clamp hoisted out of loop: min(max(v,0)) == max(min(v),0)
                        float v = fmaf(nxv[s], e.x, fmaf(nyv[s], e.y, e.z + ssn[s]));
                        mind2[s] = fminf(mind2[s], v);
                        const bool c1 = e1.y > syv[s];
                        const float xint = fmaf((syv[s] - e.y) * e.w, dx, e.x);
                        nc[s] += (int)((c0[s] != c1) && (sxv[s] < xint));
                        c0[s] = c1;
                    }
                    e = e1;
                }
                #pragma unroll
                for (int s = 0; s < 4; s++) {
                    const float dist   = sqrtf(fmaxf(mind2[s], 0.0f));
                    const float stroke = fminf(fmaxf(fmaf(wa[p], 0.5f, 0.5f) - dist, 0.0f), 1.0f);
                    const float cov    = fmaxf((float)(nc[s] & 1), stroke);
                    val[s] *= 1.0f - wa[2 + p] * cov;
                }
            }
            const float acc = (val[0] + val[1]) + (val[2] + val[3]);
            out[OUT_R + b * 784 + px] = 1.0f - 0.25f * acc;
        }
    }

    cluster_sync_all();
}

// ---------------------------------------------------------------------------
extern "C" void kernel_launch(void* const* d_in, const int* in_sizes, int n_in,
                              void* d_out, int out_size)
{
    const float* x    = (const float*)d_in[0];
    const float* eps  = (const float*)d_in[1];
    const float* ew1  = (const float*)d_in[2];
    const float* eb1  = (const float*)d_in[3];
    const float* ew2  = (const float*)d_in[4];
    const float* eb2  = (const float*)d_in[5];
    const float* muw  = (const float*)d_in[6];
    const float* mub  = (const float*)d_in[7];
    const float* lvw  = (const float*)d_in[8];
    const float* lvb  = (const float*)d_in[9];
    const float* dw1  = (const float*)d_in[10];
    const float* db1  = (const float*)d_in[11];
    const float* dw2  = (const float*)d_in[12];
    const float* db2  = (const float*)d_in[13];
    const float* cpw  = (const float*)d_in[14];
    const float* cpb  = (const float*)d_in[15];
    const float* rw1  = (const float*)d_in[16];
    const float* rb1  = (const float*)d_in[17];
    const float* rw2  = (const float*)d_in[18];
    const float* rb2  = (const float*)d_in[19];
    const float* wdw  = (const float*)d_in[20];
    const float* wdb  = (const float*)d_in[21];
    const float* alw  = (const float*)d_in[22];
    const float* alb  = (const float*)d_in[23];
    float* out = (float*)d_out;

    const int dyn = NSTAGES * STAGE_BYTES;   // 196608 bytes
    cudaFuncSetAttribute(fused_kernel, cudaFuncAttributeMaxDynamicSharedMemorySize, dyn);
    fused_kernel<<<BATCH, TPB, dyn>>>(x, eps, ew1, eb1, ew2, eb2, muw, mub, lvw, lvb,
                                      dw1, db1, dw2, db2, cpw, cpb, rw1, rb1, rw2, rb2,
                                      wdw, wdb, alw, alb, out);
}

// round 10
// speedup vs baseline: 1.0209x; 1.0209x over previous
#include <cuda_runtime.h>
#include <math.h>
#include <stdint.h>

// HierarchicalVAE fused. R10: big layers use 4-outputs/thread + LDS.128 weight
// loads with K-split smem reduction. Producer/tile table/raster same as R8.
// 832 thr: tid<512 MLP, warps 16-24 raster extras, warp 25 producer.

#define BATCH 128
#define TPB 832
#define NC 512
#define NGATE 800
#define CLUSTER 4
#define NSTAGES 3
#define STAGE_FLOATS 16384
#define STAGE_BYTES  65536
#define NT 44
#define HALFC 14.0f
#define SCALEC 12.0f

#define OUT_R  0
#define OUT_MU (BATCH*784)
#define OUT_LV (OUT_MU + BATCH*64)
#define OUT_CP (OUT_LV + BATCH*64)
#define OUT_W  (OUT_CP + BATCH*64)
#define OUT_A  (OUT_W + BATCH*2)

struct WPtrs {
    const float *ew1, *ew2, *muw, *lvw, *dw1, *dw2, *cpw, *wdw, *alw, *rw1, *rw2;
};

__device__ __forceinline__ uint32_t smem_u32(const void* p) {
    return (uint32_t)__cvta_generic_to_shared(p);
}
__device__ __forceinline__ void mbar_init(uint32_t addr, uint32_t count) {
    asm volatile("mbarrier.init.shared.b64 [%0], %1;" :: "r"(addr), "r"(count) : "memory");
}
__device__ __forceinline__ void mbar_wait(uint32_t addr, uint32_t parity) {
    asm volatile(
        "{\n\t.reg .pred P;\n"
        "W_%=:\n\t"
        "mbarrier.try_wait.parity.acquire.cta.shared::cta.b64 P, [%0], %1, 0x989680;\n\t"
        "@P bra.uni D_%=;\n\t"
        "bra.uni W_%=;\n"
        "D_%=:\n\t}"
        :: "r"(addr), "r"(parity) : "memory");
}
__device__ __forceinline__ void mbar_expect_tx(uint32_t addr, uint32_t bytes) {
    asm volatile("mbarrier.arrive.expect_tx.shared.b64 _, [%0], %1;"
                 :: "r"(addr), "r"(bytes) : "memory");
}
__device__ __forceinline__ void mbar_arrive_rank(uint32_t addr, uint32_t rank) {
    asm volatile(
        "{\n\t.reg .b32 ra;\n\t"
        "mapa.shared::cluster.u32 ra, %0, %1;\n\t"
        "mbarrier.arrive.shared::cluster.b64 _, [ra];\n\t}"
        :: "r"(addr), "r"(rank) : "memory");
}
__device__ __forceinline__ void cluster_sync_all() {
    asm volatile("barrier.cluster.arrive.aligned;" ::: "memory");
    asm volatile("barrier.cluster.wait.aligned;" ::: "memory");
}
__device__ __forceinline__ void bulk_mc(uint32_t dst, const void* src, uint32_t bytes,
                                        uint32_t mbar, uint16_t mask) {
    asm volatile(
        "cp.async.bulk.shared::cluster.global.mbarrier::complete_tx::bytes.multicast::cluster "
        "[%0], [%1], %2, [%3], %4;"
        :: "r"(dst), "l"(src), "r"(bytes), "r"(mbar), "h"(mask) : "memory");
}

__device__ __forceinline__ float seluf(float x) {
    const float sc = 1.0507009873554805f;
    const float al = 1.6732632423543772f;
    return x > 0.0f ? sc * x : sc * al * (expf(x) - 1.0f);
}
__device__ __forceinline__ float lrelu(float x) { return x >= 0.0f ? x : 0.2f * x; }
__device__ __forceinline__ float sigm(float x)  { return 1.0f / (1.0f + expf(-x)); }

// Tile table (44 tiles) — identical to R8.
__device__ __forceinline__ int tile_segs(int n, const WPtrs& p,
                                         const char* srcs[2], uint32_t szs[2]) {
    if (n < 13) { int r0 = n * 64; int rows = (r0 + 64 <= 784) ? 64 : (784 - r0);
                  srcs[0] = (const char*)(p.ew1 + r0 * 256); szs[0] = rows * 1024; return 1; }
    n -= 13;
    if (n < 4)  { srcs[0] = (const char*)(p.ew2 + n * 64 * 256); szs[0] = 65536; return 1; }
    n -= 4;
    if (n == 0) { srcs[0] = (const char*)p.muw; szs[0] = 65536; return 1; } n--;
    if (n == 0) { srcs[0] = (const char*)p.lvw; szs[0] = 65536; return 1; } n--;
    if (n < 2)  { srcs[0] = (const char*)(p.dw1 + n * 32 * 512); szs[0] = 65536; return 1; }
    n -= 2;
    if (n < 16) { srcs[0] = (const char*)(p.dw2 + n * 32 * 512); szs[0] = 65536; return 1; }
    n -= 16;
    if (n == 0) { srcs[0] = (const char*)p.cpw; szs[0] = 57344; return 1; } n--;
    if (n == 0) { srcs[0] = (const char*)p.wdw; szs[0] = 4096;
                  srcs[1] = (const char*)p.alw; szs[1] = 4096; return 2; } n--;
    if (n < 3)  { int r0 = n * 32; int rows = (r0 + 32 <= 92) ? 32 : (92 - r0);
                  srcs[0] = (const char*)(p.rw1 + r0 * 512); szs[0] = rows * 2048; return 1; }
    n -= 3;
    srcs[0] = (const char*)(p.rw2 + n * 256 * 52); szs[0] = 53248; return 1;
}

__device__ __forceinline__ void produce(int j, uint32_t bar_base, uint32_t ring_base,
                                        const WPtrs& p, uint32_t rank) {
    const int s = j % NSTAGES;
    mbar_wait(bar_base + s * 16 + 8, 1u ^ ((uint32_t)(j / NSTAGES) & 1u));
    const char* srcs[2]; uint32_t szs[2];
    int ns = tile_segs(j, p, srcs, szs);
    uint32_t total = szs[0] + ((ns > 1) ? szs[1] : 0u);
    const uint32_t full = bar_base + s * 16;
    mbar_expect_tx(full, total);
    uint32_t dst = ring_base + s * STAGE_BYTES;
    for (int k = 0; k < ns; k++) {
        uint32_t slice = szs[k] >> 2;
        bulk_mc(dst + rank * slice, srcs[k] + rank * slice, slice, full, 0xF);
        dst += szs[k];
    }
}

#define CONS_SYNC() asm volatile("bar.sync 1, %0;" :: "n"(NC) : "memory")
#define GATE_SYNC() asm volatile("bar.sync 2, %0;" :: "n"(NGATE) : "memory")

#define TILE_BEGIN() do { \
        mbar_wait(bar_base + (tn % NSTAGES) * 16, (uint32_t)(tn / NSTAGES) & 1u); \
        ws = wb + (tn % NSTAGES) * STAGE_FLOATS; } while (0)

#define TILE_END() do { __syncwarp(); \
        if ((tid & 31) == 0) { uint32_t e = bar_base + (tn % NSTAGES) * 16 + 8; \
            mbar_arrive_rank(e, 0); mbar_arrive_rank(e, 1); \
            mbar_arrive_rank(e, 2); mbar_arrive_rank(e, 3); } \
        tn++; } while (0)

__global__ void __launch_bounds__(TPB, 1) __cluster_dims__(CLUSTER, 1, 1)
fused_kernel(
    const float* __restrict__ x,    const float* __restrict__ eps,
    const float* __restrict__ ew1,  const float* __restrict__ eb1,
    const float* __restrict__ ew2,  const float* __restrict__ eb2,
    const float* __restrict__ muw,  const float* __restrict__ mub,
    const float* __restrict__ lvw,  const float* __restrict__ lvb,
    const float* __restrict__ dw1,  const float* __restrict__ db1,
    const float* __restrict__ dw2,  const float* __restrict__ db2,
    const float* __restrict__ cpw,  const float* __restrict__ cpb,
    const float* __restrict__ rw1,  const float* __restrict__ rb1,
    const float* __restrict__ rw2w, const float* __restrict__ rb2,
    const float* __restrict__ wdw,  const float* __restrict__ wdb,
    const float* __restrict__ alw,  const float* __restrict__ alb,
    float* __restrict__ out)
{
    extern __shared__ float wb[];

    const int b   = blockIdx.x;
    const int tid = threadIdx.x;

    __shared__ alignas(16) unsigned long long mbars[NSTAGES * 2];
    __shared__ float sx[784];
    __shared__ float h1[256];
    __shared__ float h2[256];
    __shared__ float muv[64];
    __shared__ float hin[92];
    __shared__ float d1[512];
    __shared__ float d2[512];
    __shared__ float r1[512];
    __shared__ float pts[52];
    __shared__ alignas(16) float red[2048];   // K-split partials
    __shared__ float red2[512];
    __shared__ float qx[64], qy[64], wa[4];
    __shared__ alignas(16) float4 pt4[64];

    WPtrs wp; wp.ew1 = ew1; wp.ew2 = ew2; wp.muw = muw; wp.lvw = lvw;
    wp.dw1 = dw1; wp.dw2 = dw2; wp.cpw = cpw; wp.wdw = wdw; wp.alw = alw;
    wp.rw1 = rw1; wp.rw2 = rw2w;

    const uint32_t bar_base  = smem_u32(mbars);
    const uint32_t ring_base = smem_u32(wb);
    uint32_t rank;
    asm("mov.u32 %0, %%cluster_ctarank;" : "=r"(rank));

    if (tid == 0) {
        #pragma unroll
        for (int s = 0; s < NSTAGES; s++) {
            mbar_init(bar_base + s * 16, 1);
            mbar_init(bar_base + s * 16 + 8, 64);
        }
    }
    __syncthreads();
    cluster_sync_all();

    if (tid >= NGATE) {
        if (tid == NGATE) {
            for (int j = 0; j < NT; j++) produce(j, bar_base, ring_base, wp, rank);
        }
    } else {
        if (tid < NC) {
            for (int i = tid; i < 784; i += NC) sx[i] = x[b * 784 + i];
            CONS_SYNC();

            int tn = 0;
            float* ws;

            // ===== enc1: 784->256, 13 tiles. kg=tid>>6 (8-way K), 4 cols/thread
            {
                const int kg = tid >> 6, q = (tid & 63) * 4;
                float a0 = 0, a1 = 0, a2 = 0, a3 = 0;
                for (int t = 0; t < 13; t++) {
                    TILE_BEGIN();
                    const int per = (t < 12) ? 8 : 2;
                    const int rb = kg * per;
                    #pragma unroll 8
                    for (int r = 0; r < per; r++) {
                        const float av = sx[t * 64 + rb + r];
                        const float4 w4 = *(const float4*)&ws[(rb + r) * 256 + q];
                        a0 = fmaf(av, w4.x, a0); a1 = fmaf(av, w4.y, a1);
                        a2 = fmaf(av, w4.z, a2); a3 = fmaf(av, w4.w, a3);
                    }
                    TILE_END();
                }
                *(float4*)&red[kg * 256 + q] = make_float4(a0, a1, a2, a3);
            }
            CONS_SYNC();
            if (tid < 256) {
                float s = eb1[tid];
                #pragma unroll
                for (int k = 0; k < 8; k++) s += red[k * 256 + tid];
                h1[tid] = lrelu(s);
            }
            CONS_SYNC();

            // ===== enc2: 256->256, 4 tiles. same mapping
            {
                const int kg = tid >> 6, q = (tid & 63) * 4;
                float a0 = 0, a1 = 0, a2 = 0, a3 = 0;
                for (int t = 0; t < 4; t++) {
                    TILE_BEGIN();
                    const int rb = kg * 8;
                    #pragma unroll 8
                    for (int r = 0; r < 8; r++) {
                        const float av = h1[t * 64 + rb + r];
                        const float4 w4 = *(const float4*)&ws[(rb + r) * 256 + q];
                        a0 = fmaf(av, w4.x, a0); a1 = fmaf(av, w4.y, a1);
                        a2 = fmaf(av, w4.z, a2); a3 = fmaf(av, w4.w, a3);
                    }
                    TILE_END();
                }
                *(float4*)&red[kg * 256 + q] = make_float4(a0, a1, a2, a3);
            }
            CONS_SYNC();
            if (tid < 256) {
                float s = eb2[tid];
                #pragma unroll
                for (int k = 0; k < 8; k++) s += red[k * 256 + tid];
                h2[tid] = lrelu(s);
            }
            CONS_SYNC();

            // ===== mu: 256->64 (1 tile), 8-way K split (as R8)
            {
                const int g = tid >> 6, l = tid & 63;
                TILE_BEGIN();
                float a = 0.0f;
                #pragma unroll 8
                for (int i = 0; i < 32; i++) {
                    int kl = g * 32 + i;
                    a = fmaf(h2[kl], ws[kl * 64 + l], a);
                }
                red[tid] = a;
                TILE_END();
            }
            CONS_SYNC();
            if (tid < 64) {
                float s = mub[tid];
                #pragma unroll
                for (int k = 0; k < 8; k++) s += red[k * 64 + tid];
                muv[tid] = s;
            }
            CONS_SYNC();

            // ===== logvar: 256->64 (1 tile)
            {
                const int g = tid >> 6, l = tid & 63;
                TILE_BEGIN();
                float a = 0.0f;
                #pragma unroll 8
                for (int i = 0; i < 32; i++) {
                    int kl = g * 32 + i;
                    a = fmaf(h2[kl], ws[kl * 64 + l], a);
                }
                red[tid] = a;
                TILE_END();
            }
            CONS_SYNC();
            if (tid < 64) {
                float lvV = lvb[tid];
                #pragma unroll
                for (int k = 0; k < 8; k++) lvV += red[k * 64 + tid];
                float m = muv[tid];
                out[OUT_MU + b * 64 + tid] = m;
                out[OUT_LV + b * 64 + tid] = lvV;
                hin[tid] = m + eps[b * 64 + tid] * expf(0.5f * lvV);
            }
            CONS_SYNC();

            // ===== dec1: 64->512, 2 tiles. kg=tid>>7 (4-way K), 4 cols/thread
            {
                const int kg = tid >> 7, q = (tid & 127) * 4;
                float a0 = 0, a1 = 0, a2 = 0, a3 = 0;
                for (int t = 0; t < 2; t++) {
                    TILE_BEGIN();
                    const int rb = kg * 8;
                    #pragma unroll 8
                    for (int r = 0; r < 8; r++) {
                        const float av = hin[t * 32 + rb + r];
                        const float4 w4 = *(const float4*)&ws[(rb + r) * 512 + q];
                        a0 = fmaf(av, w4.x, a0); a1 = fmaf(av, w4.y, a1);
                        a2 = fmaf(av, w4.z, a2); a3 = fmaf(av, w4.w, a3);
                    }
                    TILE_END();
                }
                *(float4*)&red[kg * 512 + q] = make_float4(a0, a1, a2, a3);
            }
            CONS_SYNC();
            {
                float s = db1[tid] + ((red[tid] + red[512 + tid]) + (red[1024 + tid] + red[1536 + tid]));
                d1[tid] = seluf(s);
            }
            CONS_SYNC();

            // ===== dec2: 512->512, 16 tiles. same mapping
            {
                const int kg = tid >> 7, q = (tid & 127) * 4;
                float a0 = 0, a1 = 0, a2 = 0, a3 = 0;
                for (int t = 0; t < 16; t++) {
                    TILE_BEGIN();
                    const int rb = kg * 8;
                    #pragma unroll 8
                    for (int r = 0; r < 8; r++) {
                        const float av = d1[t * 32 + rb + r];
                        const float4 w4 = *(const float4*)&ws[(rb + r) * 512 + q];
                        a0 = fmaf(av, w4.x, a0); a1 = fmaf(av, w4.y, a1);
                        a2 = fmaf(av, w4.z, a2); a3 = fmaf(av, w4.w, a3);
                    }
                    TILE_END();
                }
                *(float4*)&red[kg * 512 + q] = make_float4(a0, a1, a2, a3);
            }
            CONS_SYNC();
            {
                float s = db2[tid] + ((red[tid] + red[512 + tid]) + (red[1024 + tid] + red[1536 + tid]));
                d2[tid] = seluf(s);
            }
            CONS_SYNC();

            // ===== coarse cp: 512->28 (1 tile), 16-way K split (as R8)
            {
                const int g = tid >> 5, l = tid & 31;
                TILE_BEGIN();
                float a = 0.0f;
                if (l < 28) {
                    #pragma unroll 8
                    for (int i = 0; i < 32; i++) {
                        int kl = g * 32 + i;
                        a = fmaf(d2[kl], ws[kl * 28 + l], a);
                    }
                }
                red[tid] = a;
                TILE_END();
            }
            CONS_SYNC();
            if (tid < 28) {
                float s = cpb[tid];
                #pragma unroll
                for (int k = 0; k < 16; k++) s += red[k * 32 + tid];
                hin[64 + tid] = tanhf(s);
            }
            CONS_SYNC();

            // ===== widths + alphas (1 fused tile, as R8)
            {
                const int pp = tid >> 8, l = tid & 255;
                TILE_BEGIN();
                float aw = fmaf(d2[l], ws[l * 2 + pp], 0.0f);
                aw = fmaf(d2[l + 256], ws[(l + 256) * 2 + pp], aw);
                float aa = fmaf(d2[l], ws[1024 + l * 2 + pp], 0.0f);
                aa = fmaf(d2[l + 256], ws[1024 + (l + 256) * 2 + pp], aa);
                red[tid] = aw; red2[tid] = aa;
                TILE_END();
            }
            CONS_SYNC();
            if (tid < 2) {
                const float* rp = &red[tid * 256];
                float s0 = 0, s1 = 0, s2 = 0, s3 = 0;
                #pragma unroll
                for (int j = 0; j < 64; j++) { s0 += rp[j]; s1 += rp[64 + j]; s2 += rp[128 + j]; s3 += rp[192 + j]; }
                float wv = sigm(wdb[tid] + ((s0 + s1) + (s2 + s3))) * 2.0f + 1.0f;
                wa[tid] = wv;
                out[OUT_W + b * 2 + tid] = wv;
            } else if (tid >= 32 && tid < 34) {
                const int pA = tid - 32;
                const float* rp = &red2[pA * 256];
                float s0 = 0, s1 = 0, s2 = 0, s3 = 0;
                #pragma unroll
                for (int j = 0; j < 64; j++) { s0 += rp[j]; s1 += rp[64 + j]; s2 += rp[128 + j]; s3 += rp[192 + j]; }
                float av = sigm(alb[pA] + ((s0 + s1) + (s2 + s3)));
                wa[2 + pA] = av;
                out[OUT_A + b * 2 + pA] = av;
            }
            CONS_SYNC();

            // ===== refine1: 92->512, 3 tiles (32,32,28 rows). 4-way K, 4 cols/thread
            {
                const int kg = tid >> 7, q = (tid & 127) * 4;
                float a0 = 0, a1 = 0, a2 = 0, a3 = 0;
                for (int t = 0; t < 3; t++) {
                    TILE_BEGIN();
                    const int per = (t < 2) ? 8 : 7;
                    const int rb = kg * per;
                    #pragma unroll 8
                    for (int r = 0; r < per; r++) {
                        const float av = hin[t * 32 + rb + r];
                        const float4 w4 = *(const float4*)&ws[(rb + r) * 512 + q];
                        a0 = fmaf(av, w4.x, a0); a1 = fmaf(av, w4.y, a1);
                        a2 = fmaf(av, w4.z, a2); a3 = fmaf(av, w4.w, a3);
                    }
                    TILE_END();
                }
                *(float4*)&red[kg * 512 + q] = make_float4(a0, a1, a2, a3);
            }
            CONS_SYNC();
            {
                float s = rb1[tid] + ((red[tid] + red[512 + tid]) + (red[1024 + tid] + red[1536 + tid]));
                r1[tid] = seluf(s);
            }
            CONS_SYNC();

            // ===== refine2: 512->52 (2 tiles of 256 rows), 8-way K split (as R8)
            {
                const int g = tid >> 6, l = tid & 63;
                float a = 0.0f;
                for (int t = 0; t < 2; t++) {
                    TILE_BEGIN();
                    if (l < 52) {
                        #pragma unroll 8
                        for (int i = 0; i < 32; i++) {
                            int kl = g * 32 + i;
                            a = fmaf(r1[t * 256 + kl], ws[kl * 52 + l], a);
                        }
                    }
                    TILE_END();
                }
                red[tid] = a;
            }
            CONS_SYNC();
            if (tid < 52) {
                float s = rb2[tid];
                #pragma unroll
                for (int k = 0; k < 8; k++) s += red[k * 64 + tid];
                pts[tid] = tanhf(s) * SCALEC + HALFC;
            }
            CONS_SYNC();

            // ===== control points out + bezier sample eval
            if (tid < 64) {
                const int p = tid >> 5, rem = tid & 31;
                {
                    int s = rem >> 3, k = (rem >> 1) & 3, d = rem & 1;
                    out[OUT_CP + b * 64 + tid] = pts[p * 26 + (3 * s + k) * 2 + d];
                }
                const int ss = rem >> 3, ti = rem & 7;
                float t  = (float)ti / 7.0f;
                float mt = 1.0f - t;
                float b0 = mt * mt * mt;
                float b1 = 3.0f * mt * mt * t;
                float b2 = 3.0f * mt * t * t;
                float b3 = t * t * t;
                int base = p * 26 + (3 * ss) * 2;
                float X = b0 * pts[base + 0] + b1 * pts[base + 2] + b2 * pts[base + 4] + b3 * pts[base + 6];
                float Y = b0 * pts[base + 1] + b1 * pts[base + 3] + b2 * pts[base + 5] + b3 * pts[base + 7];
                qx[tid] = X; qy[tid] = Y;
            }
            CONS_SYNC();
            if (tid < 64) {
                const int p = tid >> 5, m = tid & 31;
                float X = qx[tid], Y = qy[tid];
                float y1 = qy[p * 32 + ((m + 1) & 31)];
                float si = __fdiv_rn(1.0f, (y1 - Y) + 1e-8f);
                pt4[tid] = make_float4(X, Y, X * X + Y * Y, si);
            }
        }

        GATE_SYNC();

        // ===== rasterizer: 1 pixel/thread (as R8)
        if (tid < 784) {
            const int px = tid;
            const int pi = px / 28, pj = px - pi * 28;
            float syv[4], sxv[4], nxv[4], nyv[4], ssn[4], val[4];
            #pragma unroll
            for (int s = 0; s < 4; s++) {
                syv[s] = (float)pi + (0.25f + 0.5f * (float)(s >> 1));
                sxv[s] = (float)pj + (0.25f + 0.5f * (float)(s & 1));
                nxv[s] = -2.0f * sxv[s];
                nyv[s] = -2.0f * syv[s];
                ssn[s] = sxv[s] * sxv[s] + syv[s] * syv[s];
                val[s] = 1.0f;
            }
            #pragma unroll
            for (int p = 0; p < 2; p++) {
                const int base = p * 32;
                float mind2[4]; int nc[4]; bool c0[4];
                float4 e = pt4[base];
                #pragma unroll
                for (int s = 0; s < 4; s++) {
                    mind2[s] = 3.402823e38f; nc[s] = 0; c0[s] = e.y > syv[s];
                }
                #pragma unroll 8
                for (int m = 0; m < 32; m++) {
                    const float4 e1 = pt4[base + ((m + 1) & 31)];
                    const float dx = e1.x - e.x;
                    #pragma unroll
                    for (int s = 0; s < 4; s++) {
                        float v = fmaf(nxv[s], e.x, fmaf(nyv[s], e.y, e.z + ssn[s]));
                        mind2[s] = fminf(mind2[s], v);
                        const bool c1 = e1.y > syv[s];
                        const float xint = fmaf((syv[s] - e.y) * e.w, dx, e.x);
                        nc[s] += (int)((c0[s] != c1) && (sxv[s] < xint));
                        c0[s] = c1;
                    }
                    e = e1;
                }
                #pragma unroll
                for (int s = 0; s < 4; s++) {
                    const float dist   = sqrtf(fmaxf(mind2[s], 0.0f));
                    const float stroke = fminf(fmaxf(fmaf(wa[p], 0.5f, 0.5f) - dist, 0.0f), 1.0f);
                    const float cov    = fmaxf((float)(nc[s] & 1), stroke);
                    val[s] *= 1.0f - wa[2 + p] * cov;
                }
            }
            const float acc = (val[0] + val[1]) + (val[2] + val[3]);
            out[OUT_R + b * 784 + px] = 1.0f - 0.25f * acc;
        }
    }

    cluster_sync_all();
}

extern "C" void kernel_launch(void* const* d_in, const int* in_sizes, int n_in,
                              void* d_out, int out_size)
{
    const float* x    = (const float*)d_in[0];
    const float* eps  = (const float*)d_in[1];
    const float* ew1  = (const float*)d_in[2];
    const float* eb1  = (const float*)d_in[3];
    const float* ew2  = (const float*)d_in[4];
    const float* eb2  = (const float*)d_in[5];
    const float* muw  = (const float*)d_in[6];
    const float* mub  = (const float*)d_in[7];
    const float* lvw  = (const float*)d_in[8];
    const float* lvb  = (const float*)d_in[9];
    const float* dw1  = (const float*)d_in[10];
    const float* db1  = (const float*)d_in[11];
    const float* dw2  = (const float*)d_in[12];
    const float* db2  = (const float*)d_in[13];
    const float* cpw  = (const float*)d_in[14];
    const float* cpb  = (const float*)d_in[15];
    const float* rw1  = (const float*)d_in[16];
    const float* rb1  = (const float*)d_in[17];
    const float* rw2  = (const float*)d_in[18];
    const float* rb2  = (const float*)d_in[19];
    const float* wdw  = (const float*)d_in[20];
    const float* wdb  = (const float*)d_in[21];
    const float* alw  = (const float*)d_in[22];
    const float* alb  = (const float*)d_in[23];
    float* out = (float*)d_out;

    const int dyn = NSTAGES * STAGE_BYTES;
    cudaFuncSetAttribute(fused_kernel, cudaFuncAttributeMaxDynamicSharedMemorySize, dyn);
    fused_kernel<<<BATCH, TPB, dyn>>>(x, eps, ew1, eb1, ew2, eb2, muw, mub, lvw, lvb,
                                      dw1, db1, dw2, db2, cpw, cpb, rw1, rb1, rw2, rb2,
                                      wdw, wdb, alw, alb, out);
}